// round 14
// baseline (speedup 1.0000x reference)
#include <cuda_runtime.h>
#include <cstdint>

#define Bc 64
#define Sc 512
#define Ic 256
#define Hc 512
#define GRID2 128
#define TPB 256
#define THc 4          // H rows per CTA in the scan (Hc / GRID2)
#define KSPL 4         // k-split per CTA
#define WPAD 516       // padded W row stride (bank-conflict avoidance)

// Scratch (sanctioned __device__ globals — no allocation in kernel_launch)
__device__ __align__(16) float g_gi[(size_t)Sc * 3 * Hc * Bc];  // [s][gate][h][b]
__device__ __align__(16) float g_h[2][Hc * Bc];                 // transposed h: [h][b], double-buffered
__device__ unsigned long long g_bar = 0ULL;                      // monotonic grid-barrier counter

__device__ __forceinline__ void fma4(float4& a, float w, float4 h) {
    a.x = fmaf(w, h.x, a.x);
    a.y = fmaf(w, h.y, a.y);
    a.z = fmaf(w, h.z, a.z);
    a.w = fmaf(w, h.w, a.w);
}

// ---------------- Phase 0: transpose h0 (1,B,H) -> g_h[0][h][b] ----------------
__global__ void k_h0(const float* __restrict__ hs) {
    int idx = blockIdx.x * blockDim.x + threadIdx.x;
    if (idx < Hc * Bc) {
        int k = idx >> 6, b = idx & 63;
        g_h[0][idx] = hs[b * Hc + k];
    }
}

// ---------------- Phase 1: gi[s][g][h][b] = sum_i W[g][h][i] * x[b][s][i] + bias[g][h] ----------------
// grid (Hc/64, Sc), 256 threads. X slice staged transposed in SMEM ([i][b], stride 68).
__global__ void __launch_bounds__(TPB) k_gi(
    const float* __restrict__ x,
    const float* __restrict__ wir, const float* __restrict__ wiz, const float* __restrict__ win,
    const float* __restrict__ bir, const float* __restrict__ biz, const float* __restrict__ bin)
{
    extern __shared__ float xt[];  // [Ic][68]
    const int s  = blockIdx.y;
    const int h0 = blockIdx.x * 64;
    const int t  = threadIdx.x;

    // Stage X^T: global-coalesced reads (i contiguous per warp), 4-way STS conflict (acceptable, one-time)
    for (int idx = t; idx < Bc * Ic; idx += TPB) {
        int b = idx >> 8, i = idx & 255;
        xt[i * 68 + b] = x[((size_t)b * Sc + s) * Ic + i];
    }
    __syncthreads();

    const int tb = t & 15, th = t >> 4;
    const int hh = h0 + th * 4;

    float4 acc[3][4];
#pragma unroll
    for (int g = 0; g < 3; g++)
#pragma unroll
        for (int hi = 0; hi < 4; hi++) acc[g][hi] = make_float4(0.f, 0.f, 0.f, 0.f);

#pragma unroll 2
    for (int k = 0; k < Ic; k += 4) {
        float4 x0 = *(const float4*)&xt[(k + 0) * 68 + tb * 4];
        float4 x1 = *(const float4*)&xt[(k + 1) * 68 + tb * 4];
        float4 x2 = *(const float4*)&xt[(k + 2) * 68 + tb * 4];
        float4 x3 = *(const float4*)&xt[(k + 3) * 68 + tb * 4];
#pragma unroll
        for (int g = 0; g < 3; g++) {
            const float* wp = (g == 0) ? wir : (g == 1) ? wiz : win;
#pragma unroll
            for (int hi = 0; hi < 4; hi++) {
                float4 w = __ldg((const float4*)&wp[(size_t)(hh + hi) * Ic + k]);
                fma4(acc[g][hi], w.x, x0);
                fma4(acc[g][hi], w.y, x1);
                fma4(acc[g][hi], w.z, x2);
                fma4(acc[g][hi], w.w, x3);
            }
        }
    }

#pragma unroll
    for (int g = 0; g < 3; g++) {
        const float* bp = (g == 0) ? bir : (g == 1) ? biz : bin;
#pragma unroll
        for (int hi = 0; hi < 4; hi++) {
            float bb = __ldg(&bp[hh + hi]);
            float4 v = acc[g][hi];
            v.x += bb; v.y += bb; v.z += bb; v.w += bb;
            *(float4*)&g_gi[(((size_t)s * 3 + g) * Hc + (hh + hi)) * Bc + tb * 4] = v;
        }
    }
}

// ---------------- Phase 2: persistent recurrent scan ----------------
// 128 CTAs (co-resident), 256 threads. CTA owns h rows [4c, 4c+4).
// Per step: stage full h (128KB) into SMEM via cp.async.cg (L1 bypass — correctness!),
// each thread accumulates 3 gate dots for a (b-quad, j, k-split) tile, partial-sum
// reduce in SMEM, fused GRU nonlinearity, write new h (transposed) + output, grid barrier.
__global__ void __launch_bounds__(TPB, 1) k_scan(
    const float* __restrict__ whr, const float* __restrict__ whz, const float* __restrict__ whn,
    const float* __restrict__ bhr, const float* __restrict__ bhz, const float* __restrict__ bhn,
    float* __restrict__ out)
{
    extern __shared__ float sm[];
    float* hsh = sm;                          // [Hc][Bc]      = 32768 floats
    float* wsh = sm + Hc * Bc;                // [3][THc][WPAD] = 6192 floats
    float* psh = wsh + 3 * THc * WPAD;        // [3][KSPL][THc][Bc] = 3072 floats

    const int t = threadIdx.x;
    const int hbase = blockIdx.x * THc;

    // Stage this CTA's W_h slice into SMEM once (resident for all 512 steps)
    for (int idx = t; idx < THc * Hc; idx += TPB) {
        int j = idx >> 9, k = idx & 511;
        int row = (hbase + j) * Hc + k;
        wsh[(0 * THc + j) * WPAD + k] = whr[row];
        wsh[(1 * THc + j) * WPAD + k] = whz[row];
        wsh[(2 * THc + j) * WPAD + k] = whn[row];
    }

    const int tb = t & 15;            // b-quad
    const int tj = (t >> 4) & 3;      // local h row
    const int ks = t >> 6;            // k-split segment
    const int k0 = ks * 128;
    const float* wr = &wsh[(0 * THc + tj) * WPAD];
    const float* wz = &wsh[(1 * THc + tj) * WPAD];
    const float* wn = &wsh[(2 * THc + tj) * WPAD];

    const int eb = t & 63;            // epilogue batch
    const int ej = t >> 6;            // epilogue local h row
    const float ebr = __ldg(&bhr[hbase + ej]);
    const float ebz = __ldg(&bhz[hbase + ej]);
    const float ebn = __ldg(&bhn[hbase + ej]);

    int cur = 0;
    for (int s = 0; s < Sc; s++) {
        // ---- stage h (transposed [h][b]) via cp.async.cg (bypasses L1: no stale lines) ----
        {
            const float* src = g_h[cur];
#pragma unroll
            for (int r = 0; r < (Hc * Bc / 4) / TPB; r++) {
                int idx = r * TPB + t;
                uint32_t da = (uint32_t)__cvta_generic_to_shared(&hsh[idx * 4]);
                const float* ga = src + (size_t)idx * 4;
                asm volatile("cp.async.cg.shared.global [%0], [%1], 16;" :: "r"(da), "l"(ga));
            }
            asm volatile("cp.async.commit_group;");
            asm volatile("cp.async.wait_group 0;" ::: "memory");
        }
        __syncthreads();

        // ---- 3 gate dot-products over this thread's k segment ----
        float4 ar = make_float4(0.f, 0.f, 0.f, 0.f), az = ar, an = ar;
#pragma unroll 4
        for (int k = k0; k < k0 + 128; k += 4) {
            float4 h0v = *(const float4*)&hsh[(k + 0) * Bc + tb * 4];
            float4 h1v = *(const float4*)&hsh[(k + 1) * Bc + tb * 4];
            float4 h2v = *(const float4*)&hsh[(k + 2) * Bc + tb * 4];
            float4 h3v = *(const float4*)&hsh[(k + 3) * Bc + tb * 4];
            float4 w4;
            w4 = *(const float4*)&wr[k];
            fma4(ar, w4.x, h0v); fma4(ar, w4.y, h1v); fma4(ar, w4.z, h2v); fma4(ar, w4.w, h3v);
            w4 = *(const float4*)&wz[k];
            fma4(az, w4.x, h0v); fma4(az, w4.y, h1v); fma4(az, w4.z, h2v); fma4(az, w4.w, h3v);
            w4 = *(const float4*)&wn[k];
            fma4(an, w4.x, h0v); fma4(an, w4.y, h1v); fma4(an, w4.z, h2v); fma4(an, w4.w, h3v);
        }
        *(float4*)&psh[((0 * KSPL + ks) * THc + tj) * Bc + tb * 4] = ar;
        *(float4*)&psh[((1 * KSPL + ks) * THc + tj) * Bc + tb * 4] = az;
        *(float4*)&psh[((2 * KSPL + ks) * THc + tj) * Bc + tb * 4] = an;
        __syncthreads();

        // ---- reduce k-split partials + GRU nonlinearity (one thread per (b, j)) ----
        float sr = 0.f, sz = 0.f, sn = 0.f;
#pragma unroll
        for (int q = 0; q < KSPL; q++) {
            sr += psh[((0 * KSPL + q) * THc + ej) * Bc + eb];
            sz += psh[((1 * KSPL + q) * THc + ej) * Bc + eb];
            sn += psh[((2 * KSPL + q) * THc + ej) * Bc + eb];
        }
        size_t gib = (((size_t)s * 3 + 0) * Hc + (hbase + ej)) * Bc + eb;
        float gr = g_gi[gib];
        float gz = g_gi[gib + (size_t)Hc * Bc];
        float gn = g_gi[gib + 2 * (size_t)Hc * Bc];
        float hprev = hsh[(hbase + ej) * Bc + eb];

        float rr = 1.f / (1.f + __expf(-(gr + sr + ebr)));
        float zz = 1.f / (1.f + __expf(-(gz + sz + ebz)));
        float nn = tanhf(gn + rr * (sn + ebn));
        float hn = (1.f - zz) * nn + zz * hprev;

        g_h[cur ^ 1][(hbase + ej) * Bc + eb] = hn;                          // transposed, coalesced
        out[((size_t)eb * Sc + s) * Hc + hbase + ej] = hn;                  // outputs (B,S,H)
        if (s == Sc - 1)
            out[(size_t)Bc * Sc * Hc + (size_t)eb * Hc + hbase + ej] = hn;  // h_final (1,B,H)

        // ---- grid barrier (generation counter; replay-safe since monotonic) ----
        __threadfence();
        __syncthreads();
        if (t == 0) {
            unsigned long long old = atomicAdd(&g_bar, 1ULL);
            unsigned long long target = (old / GRID2 + 1ULL) * (unsigned long long)GRID2;
            volatile unsigned long long* p = &g_bar;
            while (*p < target) __nanosleep(32);
            __threadfence();
        }
        __syncthreads();
        cur ^= 1;
    }
}

extern "C" void kernel_launch(void* const* d_in, const int* in_sizes, int n_in,
                              void* d_out, int out_size)
{
    const float* x   = (const float*)d_in[0];
    const float* hs  = (const float*)d_in[1];
    const float* wir = (const float*)d_in[2];
    const float* wiz = (const float*)d_in[3];
    const float* win = (const float*)d_in[4];
    const float* bir = (const float*)d_in[5];
    const float* biz = (const float*)d_in[6];
    const float* bin = (const float*)d_in[7];
    const float* whr = (const float*)d_in[8];
    const float* whz = (const float*)d_in[9];
    const float* whn = (const float*)d_in[10];
    const float* bhr = (const float*)d_in[11];
    const float* bhz = (const float*)d_in[12];
    const float* bhn = (const float*)d_in[13];
    float* out = (float*)d_out;

    // Host-side, non-stream calls: legal during capture, idempotent.
    cudaFuncSetAttribute(k_gi,   cudaFuncAttributeMaxDynamicSharedMemorySize, 69632);
    cudaFuncSetAttribute(k_scan, cudaFuncAttributeMaxDynamicSharedMemorySize, 168128);

    k_h0<<<(Hc * Bc + TPB - 1) / TPB, TPB>>>(hs);

    dim3 g1(Hc / 64, Sc);
    k_gi<<<g1, TPB, 69632>>>(x, wir, wiz, win, bir, biz, bin);

    k_scan<<<GRID2, TPB, 168128>>>(whr, whz, whn, bhr, bhz, bhn, out);
}

// round 15
// speedup vs baseline: 1.0909x; 1.0909x over previous
#include <cuda_runtime.h>
#include <cstdint>

#define Bc 64
#define Sc 512
#define Ic 256
#define Hc 512
#define GRID2 128
#define TPB 256
#define THc 4           // H rows per CTA in the scan (Hc / GRID2)
#define KSPL 4          // k-split per CTA (4 chunks of 128 k-rows)
#define WD 1028         // padded duplicated-weight row stride (floats) — bank-split

typedef unsigned long long ull;

// Scratch (sanctioned __device__ globals — no allocation in kernel_launch)
__device__ __align__(16) float g_gi[(size_t)Sc * 3 * Hc * Bc];  // [s][gate][h][b]
__device__ __align__(16) float g_h[2][Hc * Bc];                 // transposed h: [h][b], double-buffered
__device__ ull g_bar = 0ULL;                                     // monotonic grid-barrier counter

// SMEM float offsets for k_scan
#define SM_HSH   0                       // [Hc][Bc]              32768 floats
#define SM_WSH   32768                   // [3*THc][WD] dup pairs 12336 floats
#define SM_PSH   (32768 + 12336)         // [3][KSPL][THc][Bc]     3072 floats
#define SM_HOUT  (SM_PSH + 3072)         // [THc][72]               288 floats
#define SM_MBAR  (SM_HOUT + 288)         // 4 x u64 mbarriers (8-aligned: 193856B)
#define SM_SCAN_BYTES 193920

// ---- packed fp32x2 FMA (Blackwell FFMA2 path) ----
__device__ __forceinline__ void fma2(ull& acc, ull w2, ull h2) {
    asm("fma.rn.f32x2 %0, %1, %2, %0;" : "+l"(acc) : "l"(h2), "l"(w2));
}
__device__ __forceinline__ void lds2(ull& a, ull& b, uint32_t addr) {
    asm volatile("ld.shared.v2.u64 {%0,%1}, [%2];" : "=l"(a), "=l"(b) : "r"(addr));
}
__device__ __forceinline__ void sts2(uint32_t addr, ull a, ull b) {
    asm volatile("st.shared.v2.u64 [%0], {%1,%2};" :: "r"(addr), "l"(a), "l"(b));
}
__device__ __forceinline__ void mbar_init(uint32_t mb, uint32_t cnt) {
    asm volatile("mbarrier.init.shared.b64 [%0], %1;" :: "r"(mb), "r"(cnt) : "memory");
}
__device__ __forceinline__ void mbar_expect_tx(uint32_t mb, uint32_t bytes) {
    asm volatile("mbarrier.arrive.expect_tx.shared.b64 _, [%0], %1;" :: "r"(mb), "r"(bytes) : "memory");
}
__device__ __forceinline__ void mbar_wait(uint32_t mb, uint32_t parity) {
    asm volatile(
        "{\n\t.reg .pred P;\n\t"
        "WLOOP%=:\n\t"
        "mbarrier.try_wait.parity.acquire.cta.shared::cta.b64 P, [%0], %1, 0x989680;\n\t"
        "@P bra WDONE%=;\n\t"
        "bra WLOOP%=;\n\t"
        "WDONE%=:\n\t}"
        :: "r"(mb), "r"(parity) : "memory");
}
__device__ __forceinline__ void bulk_cp(uint32_t dst, const float* src, uint32_t bytes, uint32_t mb) {
    asm volatile("cp.async.bulk.shared::cluster.global.mbarrier::complete_tx::bytes [%0], [%1], %2, [%3];"
                 :: "r"(dst), "l"(src), "r"(bytes), "r"(mb) : "memory");
}

__device__ __forceinline__ void fma4(float4& a, float w, float4 h) {
    a.x = fmaf(w, h.x, a.x);
    a.y = fmaf(w, h.y, a.y);
    a.z = fmaf(w, h.z, a.z);
    a.w = fmaf(w, h.w, a.w);
}

// ---------------- Phase 0: transpose h0 (1,B,H) -> g_h[0][h][b] ----------------
__global__ void k_h0(const float* __restrict__ hs) {
    int idx = blockIdx.x * blockDim.x + threadIdx.x;
    if (idx < Hc * Bc) {
        int k = idx >> 6, b = idx & 63;
        g_h[0][idx] = hs[b * Hc + k];
    }
}

// ---------------- Phase 1: gi[s][g][h][b] = sum_i W[g][h][i] * x[b][s][i] + bias[g][h] ----------------
__global__ void __launch_bounds__(TPB) k_gi(
    const float* __restrict__ x,
    const float* __restrict__ wir, const float* __restrict__ wiz, const float* __restrict__ win,
    const float* __restrict__ bir, const float* __restrict__ biz, const float* __restrict__ bin)
{
    extern __shared__ float xt[];  // [Ic][68]
    const int s  = blockIdx.y;
    const int h0 = blockIdx.x * 64;
    const int t  = threadIdx.x;

    for (int idx = t; idx < Bc * Ic; idx += TPB) {
        int b = idx >> 8, i = idx & 255;
        xt[i * 68 + b] = x[((size_t)b * Sc + s) * Ic + i];
    }
    __syncthreads();

    const int tb = t & 15, th = t >> 4;
    const int hh = h0 + th * 4;

    float4 acc[3][4];
#pragma unroll
    for (int g = 0; g < 3; g++)
#pragma unroll
        for (int hi = 0; hi < 4; hi++) acc[g][hi] = make_float4(0.f, 0.f, 0.f, 0.f);

#pragma unroll 2
    for (int k = 0; k < Ic; k += 4) {
        float4 x0 = *(const float4*)&xt[(k + 0) * 68 + tb * 4];
        float4 x1 = *(const float4*)&xt[(k + 1) * 68 + tb * 4];
        float4 x2 = *(const float4*)&xt[(k + 2) * 68 + tb * 4];
        float4 x3 = *(const float4*)&xt[(k + 3) * 68 + tb * 4];
#pragma unroll
        for (int g = 0; g < 3; g++) {
            const float* wp = (g == 0) ? wir : (g == 1) ? wiz : win;
#pragma unroll
            for (int hi = 0; hi < 4; hi++) {
                float4 w = __ldg((const float4*)&wp[(size_t)(hh + hi) * Ic + k]);
                fma4(acc[g][hi], w.x, x0);
                fma4(acc[g][hi], w.y, x1);
                fma4(acc[g][hi], w.z, x2);
                fma4(acc[g][hi], w.w, x3);
            }
        }
    }

#pragma unroll
    for (int g = 0; g < 3; g++) {
        const float* bp = (g == 0) ? bir : (g == 1) ? biz : bin;
#pragma unroll
        for (int hi = 0; hi < 4; hi++) {
            float bb = __ldg(&bp[hh + hi]);
            float4 v = acc[g][hi];
            v.x += bb; v.y += bb; v.z += bb; v.w += bb;
            *(float4*)&g_gi[(((size_t)s * 3 + g) * Hc + (hh + hi)) * Bc + tb * 4] = v;
        }
    }
}

// ---------------- Phase 2: persistent recurrent scan ----------------
// 128 CTAs (1/SM, co-resident). CTA owns h rows [4c, 4c+4).
// Per step: 4x cp.async.bulk stages h (32KB chunks, per-chunk mbarrier so compute
// starts as soon as a warp's own chunk lands), packed f32x2 dot products against
// SMEM-resident duplicated weights, k-split reduce, fused GRU nonlinearity,
// release/acquire grid barrier.
__global__ void __launch_bounds__(TPB, 1) k_scan(
    const float* __restrict__ whr, const float* __restrict__ whz, const float* __restrict__ whn,
    const float* __restrict__ bhr, const float* __restrict__ bhz, const float* __restrict__ bhn,
    float* __restrict__ out)
{
    extern __shared__ float sm[];
    const uint32_t smb = (uint32_t)__cvta_generic_to_shared(sm);
    const uint32_t hsh_a  = smb + SM_HSH  * 4;
    const uint32_t wsh_a  = smb + SM_WSH  * 4;
    const uint32_t psh_a  = smb + SM_PSH  * 4;
    const uint32_t mbar_a = smb + SM_MBAR * 4;
    float* hsh  = sm + SM_HSH;
    float* wsm  = sm + SM_WSH;
    float* psh  = sm + SM_PSH;
    float* hout = sm + SM_HOUT;

    const int t = threadIdx.x;
    const int hbase = blockIdx.x * THc;

    // mbarrier init (once per launch)
    if (t == 0) {
#pragma unroll
        for (int c = 0; c < KSPL; c++) mbar_init(mbar_a + c * 8, 1);
    }

    // Stage duplicated W_h slice into SMEM once (resident for all 512 steps)
    for (int idx = t; idx < THc * Hc; idx += TPB) {
        int j = idx >> 9, k = idx & 511;
        int row = (hbase + j) * Hc + k;
        float vr = whr[row], vz = whz[row], vn = whn[row];
        wsm[(0 * THc + j) * WD + 2 * k]     = vr;
        wsm[(0 * THc + j) * WD + 2 * k + 1] = vr;
        wsm[(1 * THc + j) * WD + 2 * k]     = vz;
        wsm[(1 * THc + j) * WD + 2 * k + 1] = vz;
        wsm[(2 * THc + j) * WD + 2 * k]     = vn;
        wsm[(2 * THc + j) * WD + 2 * k + 1] = vn;
    }
    asm volatile("fence.proxy.async;" ::: "memory");
    __syncthreads();

    const int tb = t & 15;            // b-quad
    const int tj = (t >> 4) & 3;      // local h row
    const int ks = t >> 6;            // k-split chunk (uniform per warp)
    const int k0 = ks * 128;

    const uint32_t haddr0 = hsh_a + (uint32_t)(k0 * Bc + tb * 4) * 4;
    const uint32_t wr_a = wsh_a + (uint32_t)((0 * THc + tj) * WD + 2 * k0) * 4;
    const uint32_t wz_a = wsh_a + (uint32_t)((1 * THc + tj) * WD + 2 * k0) * 4;
    const uint32_t wn_a = wsh_a + (uint32_t)((2 * THc + tj) * WD + 2 * k0) * 4;

    const int eb = t & 63;            // epilogue batch
    const int ej = t >> 6;            // epilogue local h row
    const float ebr = __ldg(&bhr[hbase + ej]);
    const float ebz = __ldg(&bhz[hbase + ej]);
    const float ebn = __ldg(&bhn[hbase + ej]);
    const int ob = t >> 2;            // out-store batch
    const int oj = t & 3;             // out-store local h row

    int cur = 0;
    for (int s = 0; s < Sc; s++) {
        // ---- stage h via 4x cp.async.bulk (one 32KB chunk per mbarrier) ----
        if ((t & 63) == 0) {
            int c = t >> 6;
            asm volatile("fence.proxy.async;" ::: "memory");
            mbar_expect_tx(mbar_a + c * 8, 32768u);
            bulk_cp(hsh_a + (uint32_t)c * 32768u, g_h[cur] + c * 8192, 32768u, mbar_a + c * 8);
        }

        // ---- prefetch gi for the epilogue (hides DRAM latency under the dots) ----
        size_t gib = (((size_t)s * 3 + 0) * Hc + (hbase + ej)) * Bc + eb;
        float gr = __ldg(&g_gi[gib]);
        float gz = __ldg(&g_gi[gib + (size_t)Hc * Bc]);
        float gn = __ldg(&g_gi[gib + 2 * (size_t)Hc * Bc]);

        // ---- wait only for this warp's chunk ----
        mbar_wait(mbar_a + ks * 8, (uint32_t)(s & 1));

        // ---- 3 gate dot-products, packed f32x2 ----
        ull ar0 = 0, ar1 = 0, az0 = 0, az1 = 0, an0 = 0, an1 = 0;
#pragma unroll 8
        for (int kk = 0; kk < 128; kk += 4) {
            ull h0a, h0b, h1a, h1b, h2a, h2b, h3a, h3b;
            lds2(h0a, h0b, haddr0 + (uint32_t)(kk + 0) * 256);
            lds2(h1a, h1b, haddr0 + (uint32_t)(kk + 1) * 256);
            lds2(h2a, h2b, haddr0 + (uint32_t)(kk + 2) * 256);
            lds2(h3a, h3b, haddr0 + (uint32_t)(kk + 3) * 256);
            ull w0, w1, w2, w3;
            lds2(w0, w1, wr_a + (uint32_t)kk * 8);
            lds2(w2, w3, wr_a + (uint32_t)kk * 8 + 16);
            fma2(ar0, w0, h0a); fma2(ar1, w0, h0b);
            fma2(ar0, w1, h1a); fma2(ar1, w1, h1b);
            fma2(ar0, w2, h2a); fma2(ar1, w2, h2b);
            fma2(ar0, w3, h3a); fma2(ar1, w3, h3b);
            lds2(w0, w1, wz_a + (uint32_t)kk * 8);
            lds2(w2, w3, wz_a + (uint32_t)kk * 8 + 16);
            fma2(az0, w0, h0a); fma2(az1, w0, h0b);
            fma2(az0, w1, h1a); fma2(az1, w1, h1b);
            fma2(az0, w2, h2a); fma2(az1, w2, h2b);
            fma2(az0, w3, h3a); fma2(az1, w3, h3b);
            lds2(w0, w1, wn_a + (uint32_t)kk * 8);
            lds2(w2, w3, wn_a + (uint32_t)kk * 8 + 16);
            fma2(an0, w0, h0a); fma2(an1, w0, h0b);
            fma2(an0, w1, h1a); fma2(an1, w1, h1b);
            fma2(an0, w2, h2a); fma2(an1, w2, h2b);
            fma2(an0, w3, h3a); fma2(an1, w3, h3b);
        }
        sts2(psh_a + (uint32_t)(((0 * KSPL + ks) * THc + tj) * Bc + tb * 4) * 4, ar0, ar1);
        sts2(psh_a + (uint32_t)(((1 * KSPL + ks) * THc + tj) * Bc + tb * 4) * 4, az0, az1);
        sts2(psh_a + (uint32_t)(((2 * KSPL + ks) * THc + tj) * Bc + tb * 4) * 4, an0, an1);
        __syncthreads();

        // ---- reduce k-split partials + fused GRU nonlinearity ----
        float sr = 0.f, sz = 0.f, sn = 0.f;
#pragma unroll
        for (int q = 0; q < KSPL; q++) {
            sr += psh[((0 * KSPL + q) * THc + ej) * Bc + eb];
            sz += psh[((1 * KSPL + q) * THc + ej) * Bc + eb];
            sn += psh[((2 * KSPL + q) * THc + ej) * Bc + eb];
        }
        float hprev = hsh[(hbase + ej) * Bc + eb];

        float er = __expf(-(gr + sr + ebr));
        float rr = __fdividef(1.f, 1.f + er);
        float ez = __expf(-(gz + sz + ebz));
        float zz = __fdividef(1.f, 1.f + ez);
        float xn = gn + rr * (sn + ebn);
        float en = __expf(2.f * xn);
        float nn = 1.f - __fdividef(2.f, en + 1.f);   // tanh, saturates cleanly
        float hn = (1.f - zz) * nn + zz * hprev;

        g_h[cur ^ 1][(hbase + ej) * Bc + eb] = hn;    // transposed, coalesced
        hout[ej * 72 + eb] = hn;                       // repack for coalesced out-store
        __syncthreads();                               // (A) h STGs + hout done

        // ---- coalesced out-store (overlaps barrier arrival of other CTAs) ----
        {
            float v = hout[oj * 72 + ob];
            out[((size_t)ob * Sc + s) * Hc + hbase + oj] = v;
            if (s == Sc - 1)
                out[(size_t)Bc * Sc * Hc + (size_t)ob * Hc + hbase + oj] = v;  // h_final
        }

        // ---- grid barrier: release-atomic arrival, acquire-load spin ----
        if (t == 0) {
            ull old;
            asm volatile("atom.release.gpu.global.add.u64 %0, [%1], %2;"
                         : "=l"(old) : "l"(&g_bar), "l"(1ULL) : "memory");
            ull target = (old / GRID2 + 1ULL) * (ull)GRID2;
            while (true) {
                ull v;
                asm volatile("ld.acquire.gpu.global.u64 %0, [%1];" : "=l"(v) : "l"(&g_bar) : "memory");
                if (v >= target) break;
                __nanosleep(16);
            }
        }
        __syncthreads();                               // (B)
        cur ^= 1;
    }
}

extern "C" void kernel_launch(void* const* d_in, const int* in_sizes, int n_in,
                              void* d_out, int out_size)
{
    const float* x   = (const float*)d_in[0];
    const float* hs  = (const float*)d_in[1];
    const float* wir = (const float*)d_in[2];
    const float* wiz = (const float*)d_in[3];
    const float* win = (const float*)d_in[4];
    const float* bir = (const float*)d_in[5];
    const float* biz = (const float*)d_in[6];
    const float* bin = (const float*)d_in[7];
    const float* whr = (const float*)d_in[8];
    const float* whz = (const float*)d_in[9];
    const float* whn = (const float*)d_in[10];
    const float* bhr = (const float*)d_in[11];
    const float* bhz = (const float*)d_in[12];
    const float* bhn = (const float*)d_in[13];
    float* out = (float*)d_out;

    cudaFuncSetAttribute(k_gi,   cudaFuncAttributeMaxDynamicSharedMemorySize, 69632);
    cudaFuncSetAttribute(k_scan, cudaFuncAttributeMaxDynamicSharedMemorySize, SM_SCAN_BYTES);

    k_h0<<<(Hc * Bc + TPB - 1) / TPB, TPB>>>(hs);

    dim3 g1(Hc / 64, Sc);
    k_gi<<<g1, TPB, 69632>>>(x, wir, wiz, win, bir, biz, bin);

    k_scan<<<GRID2, TPB, SM_SCAN_BYTES>>>(whr, whz, whn, bhr, bhz, bhn, out);
}

// round 17
// speedup vs baseline: 1.2890x; 1.1816x over previous
#include <cuda_runtime.h>
#include <cstdint>

#define Bc 64
#define Sc 512
#define Ic 256
#define Hc 512
#define TPB 256
#define NJG 16     // j-groups (CTAs per batch-group)
#define NBG 8      // b-groups
#define JPC 32     // H rows per CTA
#define BPC 8      // batches per CTA
#define KS  8      // k-split warps
#define KPT 64     // k per thread

typedef unsigned long long ull;

// Scratch (__device__ globals — no allocation anywhere)
__device__ __align__(16) float g_gi[(size_t)Sc * 3 * NBG * Hc * BPC]; // [s][g][bg][j][b8]
__device__ __align__(16) float g_h[2][NBG][Hc][BPC];                  // [buf][bg][k][b8]
__device__ ull g_bars[NBG][16];                                        // 128B-padded counters

// scan SMEM float offsets
#define SM_W    0                        // [3][512][32]  = 49152 floats (192 KB)
#define SM_H    49152                    // [512][8]      = 4096  (16 KB)
#define SM_P    (49152 + 4096)           // partials      = 4096  (16 KB, two-pass)
#define SM_HOUT (SM_P + 4096)            // [8][36]       = 288
#define SM_SCAN_BYTES ((SM_HOUT + 288) * 4)   // 230528 B

__device__ __forceinline__ void fma2(ull& acc, ull w2, ull h2) {
    asm("fma.rn.f32x2 %0, %1, %2, %0;" : "+l"(acc) : "l"(h2), "l"(w2));
}
__device__ __forceinline__ void lds2(ull& a, ull& b, uint32_t addr) {
    asm("ld.shared.v2.u64 {%0,%1}, [%2];" : "=l"(a), "=l"(b) : "r"(addr));
}
__device__ __forceinline__ void sts2(uint32_t addr, ull a, ull b) {
    asm volatile("st.shared.v2.u64 [%0], {%1,%2};" :: "r"(addr), "l"(a), "l"(b));
}
__device__ __forceinline__ float ldsf(uint32_t addr) {
    float v; asm("ld.shared.f32 %0, [%1];" : "=f"(v) : "r"(addr)); return v;
}
__device__ __forceinline__ ull pk(float w) {
    ull r; uint32_t u = __float_as_uint(w);
    asm("mov.b64 %0, {%1,%1};" : "=l"(r) : "r"(u)); return r;
}

// ---------------- Phase 0: h0 (1,B,H) -> g_h[0][bg][k][b8] ----------------
__global__ void k_h0(const float* __restrict__ hs) {
    int o = blockIdx.x * blockDim.x + threadIdx.x;
    if (o < Hc * Bc) {
        int b8 = o & 7, k = (o >> 3) & 511, bg = o >> 12;
        g_h[0][bg][k][b8] = hs[(bg * 8 + b8) * Hc + k];
    }
}

// ---------------- Phase 1: gi = x @ W_i^T + b_i, packed f32x2 ----------------
__global__ void __launch_bounds__(TPB) k_gi(
    const float* __restrict__ x,
    const float* __restrict__ wir, const float* __restrict__ wiz, const float* __restrict__ win,
    const float* __restrict__ bir, const float* __restrict__ biz, const float* __restrict__ bin)
{
    extern __shared__ float xt[];  // [Ic][68], transposed x slice
    const int s  = blockIdx.y;
    const int h0 = blockIdx.x * 64;
    const int t  = threadIdx.x;

    for (int idx = t; idx < Bc * Ic; idx += TPB) {
        int b = idx >> 8, i = idx & 255;
        xt[i * 68 + b] = x[((size_t)b * Sc + s) * Ic + i];
    }
    __syncthreads();

    const int tb = t & 15, th = t >> 4;
    const int hh = h0 + th * 4;
    const uint32_t xb = (uint32_t)__cvta_generic_to_shared(xt) + tb * 16;

    ull acc[3][4][2];
#pragma unroll
    for (int g = 0; g < 3; g++)
#pragma unroll
        for (int hi = 0; hi < 4; hi++) { acc[g][hi][0] = 0; acc[g][hi][1] = 0; }

#pragma unroll 2
    for (int k = 0; k < Ic; k += 4) {
        ull x0a, x0b, x1a, x1b, x2a, x2b, x3a, x3b;
        lds2(x0a, x0b, xb + (uint32_t)(k + 0) * 272);
        lds2(x1a, x1b, xb + (uint32_t)(k + 1) * 272);
        lds2(x2a, x2b, xb + (uint32_t)(k + 2) * 272);
        lds2(x3a, x3b, xb + (uint32_t)(k + 3) * 272);
#pragma unroll
        for (int g = 0; g < 3; g++) {
            const float* wp = (g == 0) ? wir : (g == 1) ? wiz : win;
#pragma unroll
            for (int hi = 0; hi < 4; hi++) {
                float4 w = __ldg((const float4*)&wp[(size_t)(hh + hi) * Ic + k]);
                ull wx = pk(w.x), wy = pk(w.y), wz = pk(w.z), ww = pk(w.w);
                fma2(acc[g][hi][0], wx, x0a); fma2(acc[g][hi][1], wx, x0b);
                fma2(acc[g][hi][0], wy, x1a); fma2(acc[g][hi][1], wy, x1b);
                fma2(acc[g][hi][0], wz, x2a); fma2(acc[g][hi][1], wz, x2b);
                fma2(acc[g][hi][0], ww, x3a); fma2(acc[g][hi][1], ww, x3b);
            }
        }
    }

    const int bg = tb >> 1, boff = (tb & 1) * 4;
#pragma unroll
    for (int g = 0; g < 3; g++) {
        const float* bp = (g == 0) ? bir : (g == 1) ? biz : bin;
#pragma unroll
        for (int hi = 0; hi < 4; hi++) {
            float bb = __ldg(&bp[hh + hi]);
            float2 lo = *reinterpret_cast<float2*>(&acc[g][hi][0]);
            float2 hi2 = *reinterpret_cast<float2*>(&acc[g][hi][1]);
            float4 v = make_float4(lo.x + bb, lo.y + bb, hi2.x + bb, hi2.y + bb);
            *(float4*)&g_gi[((((size_t)s * 3 + g) * NBG + bg) * Hc + (hh + hi)) * BPC + boff] = v;
        }
    }
}

// ---------------- Phase 2: persistent scan, 16 jg-CTAs x 8 independent bg-groups ----------------
__global__ void __launch_bounds__(TPB, 1) k_scan(
    const float* __restrict__ whr, const float* __restrict__ whz, const float* __restrict__ whn,
    const float* __restrict__ bhr, const float* __restrict__ bhz, const float* __restrict__ bhn,
    float* __restrict__ out)
{
    extern __shared__ float sm[];
    const uint32_t smb = (uint32_t)__cvta_generic_to_shared(sm);
    float* hsh  = sm + SM_H;
    float* psh  = sm + SM_P;
    float* hout = sm + SM_HOUT;

    const int t  = threadIdx.x;
    const int bg = blockIdx.x & 7;
    const int jg = blockIdx.x >> 3;
    const int jbase = jg * JPC;

    // Stage W_h slice transposed: wsh[(g*512+k)*32 + jl]  (conflict-free STS; strided LDG hits L2, one-time)
    for (int idx = t; idx < JPC * Hc; idx += TPB) {
        int jl = idx & 31, k = idx >> 5;
        size_t row = (size_t)(jbase + jl) * Hc + k;
        sm[SM_W + ((size_t)0 * Hc + k) * JPC + jl] = __ldg(&whr[row]);
        sm[SM_W + ((size_t)1 * Hc + k) * JPC + jl] = __ldg(&whz[row]);
        sm[SM_W + ((size_t)2 * Hc + k) * JPC + jl] = __ldg(&whn[row]);
    }
    __syncthreads();

    const int j  = t & 31;            // j lane (warp = all 32 j)
    const int ks = t >> 5;            // k-split warp
    const int k0 = ks * KPT;
    const uint32_t hA  = smb + SM_H * 4 + (uint32_t)k0 * 32;
    const uint32_t wA0 = smb + (uint32_t)(SM_W + (0 * Hc + k0) * JPC + j) * 4;
    const uint32_t wA1 = smb + (uint32_t)(SM_W + (1 * Hc + k0) * JPC + j) * 4;
    const uint32_t wA2 = smb + (uint32_t)(SM_W + (2 * Hc + k0) * JPC + j) * 4;
    const uint32_t pA  = smb + SM_P * 4;

    const int ej = t >> 3, eb = t & 7;       // epilogue (j,b)
    const float br = __ldg(&bhr[jbase + ej]);
    const float bz = __ldg(&bhz[jbase + ej]);
    const float bn = __ldg(&bhn[jbase + ej]);
    const int oj = t & 31, ob = t >> 5;      // out-store (j,b)
    ull* mycnt = &g_bars[bg][0];

    int cur = 0;
    for (int s = 0; s < Sc; s++) {
        // ---- stage this bg's h slice (16 KB) via cp.async.cg (L1-bypassing) ----
        const float* src = &g_h[cur][bg][0][0];
#pragma unroll
        for (int r = 0; r < 4; r++) {
            int i4 = r * TPB + t;
            uint32_t da = smb + SM_H * 4 + (uint32_t)i4 * 16;
            asm volatile("cp.async.cg.shared.global [%0], [%1], 16;" :: "r"(da), "l"(src + (size_t)i4 * 4));
        }
        asm volatile("cp.async.commit_group;");

        // ---- gi prefetch (DRAM latency hidden under the stage wait) ----
        size_t gib = ((((size_t)s * 3 + 0) * NBG + bg) * Hc + (jbase + ej)) * BPC + eb;
        float gr = __ldg(&g_gi[gib]);
        float gz = __ldg(&g_gi[gib + (size_t)NBG * Hc * BPC]);
        float gn = __ldg(&g_gi[gib + 2 * (size_t)NBG * Hc * BPC]);

        asm volatile("cp.async.wait_group 0;" ::: "memory");
        __syncthreads();

        // ---- 3 gate dots: warp-broadcast h, coalesced w, packed f32x2 ----
        ull a0[4] = {0,0,0,0}, a1[4] = {0,0,0,0}, a2[4] = {0,0,0,0};
#pragma unroll 4
        for (int kk = 0; kk < KPT; kk++) {
            ull hx, hy, hz_, hw;
            lds2(hx, hy, hA + (uint32_t)kk * 32);
            lds2(hz_, hw, hA + (uint32_t)kk * 32 + 16);
            ull w0 = pk(ldsf(wA0 + (uint32_t)kk * 128));
            ull w1 = pk(ldsf(wA1 + (uint32_t)kk * 128));
            ull w2 = pk(ldsf(wA2 + (uint32_t)kk * 128));
            fma2(a0[0], w0, hx); fma2(a0[1], w0, hy); fma2(a0[2], w0, hz_); fma2(a0[3], w0, hw);
            fma2(a1[0], w1, hx); fma2(a1[1], w1, hy); fma2(a1[2], w1, hz_); fma2(a1[3], w1, hw);
            fma2(a2[0], w2, hx); fma2(a2[1], w2, hy); fma2(a2[2], w2, hz_); fma2(a2[3], w2, hw);
        }

        // ---- pass 1: r,z partials (16 KB buffer) ----
        uint32_t pr = pA + (uint32_t)((0 * KS + ks) * JPC + j) * 32;
        uint32_t pz = pA + (uint32_t)((1 * KS + ks) * JPC + j) * 32;
        sts2(pr, a0[0], a0[1]); sts2(pr + 16, a0[2], a0[3]);
        sts2(pz, a1[0], a1[1]); sts2(pz + 16, a1[2], a1[3]);
        __syncthreads();
        float sr = 0.f, sz = 0.f;
#pragma unroll
        for (int q = 0; q < KS; q++) {
            sr += psh[((0 * KS + q) * JPC + ej) * BPC + eb];
            sz += psh[((1 * KS + q) * JPC + ej) * BPC + eb];
        }
        float hprev = hsh[(jbase + ej) * BPC + eb];
        __syncthreads();   // pass-1 loads done before reuse

        // ---- pass 2: n partials (reuse buffer) ----
        uint32_t pn = pA + (uint32_t)(ks * JPC + j) * 32;
        sts2(pn, a2[0], a2[1]); sts2(pn + 16, a2[2], a2[3]);
        __syncthreads();
        float sn = 0.f;
#pragma unroll
        for (int q = 0; q < KS; q++) sn += psh[(q * JPC + ej) * BPC + eb];

        // ---- fused GRU nonlinearity ----
        float rr = __fdividef(1.f, 1.f + __expf(-(gr + sr + br)));
        float zz = __fdividef(1.f, 1.f + __expf(-(gz + sz + bz)));
        float xn = gn + rr * (sn + bn);
        float nn = 1.f - __fdividef(2.f, __expf(2.f * xn) + 1.f);  // tanh, saturates cleanly
        float hn = (1.f - zz) * nn + zz * hprev;

        g_h[cur ^ 1][bg][jbase + ej][eb] = hn;   // coalesced 128B/warp
        hout[eb * 36 + ej] = hn;                  // conflict-free repack
        __syncthreads();

        // ---- coalesced out-store ----
        {
            float v = hout[ob * 36 + oj];
            out[(((size_t)(bg * BPC + ob)) * Sc + s) * Hc + jbase + oj] = v;
            if (s == Sc - 1)
                out[(size_t)Bc * Sc * Hc + (size_t)(bg * BPC + ob) * Hc + jbase + oj] = v;
        }

        // ---- per-bg-group barrier (16 arrivals; release/acquire + CTA sync transitivity) ----
        if (t == 0) {
            ull old;
            asm volatile("atom.release.gpu.global.add.u64 %0, [%1], %2;"
                         : "=l"(old) : "l"(mycnt), "l"(1ULL) : "memory");
            ull target = (old / NJG + 1ULL) * (ull)NJG;
            while (true) {
                ull v;
                asm volatile("ld.acquire.gpu.global.u64 %0, [%1];" : "=l"(v) : "l"(mycnt) : "memory");
                if (v >= target) break;
                __nanosleep(8);
            }
        }
        __syncthreads();
        cur ^= 1;
    }
}

extern "C" void kernel_launch(void* const* d_in, const int* in_sizes, int n_in,
                              void* d_out, int out_size)
{
    const float* x   = (const float*)d_in[0];
    const float* hs  = (const float*)d_in[1];
    const float* wir = (const float*)d_in[2];
    const float* wiz = (const float*)d_in[3];
    const float* win = (const float*)d_in[4];
    const float* bir = (const float*)d_in[5];
    const float* biz = (const float*)d_in[6];
    const float* bin = (const float*)d_in[7];
    const float* whr = (const float*)d_in[8];
    const float* whz = (const float*)d_in[9];
    const float* whn = (const float*)d_in[10];
    const float* bhr = (const float*)d_in[11];
    const float* bhz = (const float*)d_in[12];
    const float* bhn = (const float*)d_in[13];
    float* out = (float*)d_out;

    cudaFuncSetAttribute(k_gi,   cudaFuncAttributeMaxDynamicSharedMemorySize, 69632);
    cudaFuncSetAttribute(k_scan, cudaFuncAttributeMaxDynamicSharedMemorySize, SM_SCAN_BYTES);

    k_h0<<<(Hc * Bc + TPB - 1) / TPB, TPB>>>(hs);

    dim3 g1(Hc / 64, Sc);
    k_gi<<<g1, TPB, 69632>>>(x, wir, wiz, win, bir, biz, bin);

    k_scan<<<NJG * NBG, TPB, SM_SCAN_BYTES>>>(whr, whz, whn, bhr, bhz, bhn, out);
}